// round 2
// baseline (speedup 1.0000x reference)
#include <cuda_runtime.h>
#include <math.h>

typedef unsigned long long ull;

#define MAXN  50000
#define FDIM  128
#define TMR   192          // block row tile
#define NTH   192          // threads per block
#define LDA   132          // padded A row (floats)
#define PLANE ((size_t)MAXN * FDIM)

// -------- scratch (allocation-free: __device__ globals) --------
__device__ float g_M0[MAXN * FDIM];
__device__ float g_M1[3][MAXN * FDIM];
__device__ float g_M2[3][MAXN * FDIM];
__device__ float g_M3[3][MAXN * FDIM];
__device__ float g_ms[MAXN * FDIM];
__device__ float g_mv[3][MAXN * FDIM];

// -------- packed fp32 helpers (sm_100+ FFMA2) --------
__device__ __forceinline__ void fma2(ull& d, ull a, ull b) {
    asm("fma.rn.f32x2 %0, %1, %2, %0;" : "+l"(d) : "l"(a), "l"(b));
}
__device__ __forceinline__ ull dup2(float x) {
    ull r; asm("mov.b64 %0, {%1, %1};" : "=l"(r) : "f"(x)); return r;
}
union U64F2 { ull u; float2 f; };

// -------- GEMM core: per-thread 16 rows x 8 cols (4 col-pairs) --------
// As: [TMR][LDA] row-major padded. Bs: [128][128] row-major.
// trow = tid>>4 (0..11), tcol = tid&15 (0..15).
__device__ __forceinline__ void gemm_core(const float* __restrict__ As,
                                          const float* __restrict__ Bs,
                                          ull acc[16][4], int trow, int tcol) {
    const float* a = As + trow * 16 * LDA;
    const float* b = Bs + tcol * 8;
#pragma unroll 2
    for (int k = 0; k < FDIM; k += 2) {
        ulonglong2 b0a = *(const ulonglong2*)(b + (size_t)k * FDIM);
        ulonglong2 b0b = *(const ulonglong2*)(b + (size_t)k * FDIM + 4);
        ulonglong2 b1a = *(const ulonglong2*)(b + (size_t)(k + 1) * FDIM);
        ulonglong2 b1b = *(const ulonglong2*)(b + (size_t)(k + 1) * FDIM + 4);
#pragma unroll
        for (int i = 0; i < 16; ++i) {
            float2 av = *(const float2*)(a + i * LDA + k);
            ull a0 = dup2(av.x);
            fma2(acc[i][0], a0, b0a.x);
            fma2(acc[i][1], a0, b0a.y);
            fma2(acc[i][2], a0, b0b.x);
            fma2(acc[i][3], a0, b0b.y);
            ull a1 = dup2(av.y);
            fma2(acc[i][0], a1, b1a.x);
            fma2(acc[i][1], a1, b1a.y);
            fma2(acc[i][2], a1, b1b.x);
            fma2(acc[i][3], a1, b1b.y);
        }
    }
}

__device__ __forceinline__ void zero_acc(ull acc[16][4]) {
#pragma unroll
    for (int i = 0; i < 16; ++i)
#pragma unroll
        for (int j = 0; j < 4; ++j) acc[i][j] = 0ull;
}

__device__ __forceinline__ void load_A_rm(float* As, const float* __restrict__ src,
                                          int n0, int N) {
    for (int i = threadIdx.x; i < TMR * 32; i += NTH) {
        int r = i >> 5;
        int c4 = (i & 31) * 4;
        float4 v = make_float4(0.f, 0.f, 0.f, 0.f);
        if (n0 + r < N) v = *(const float4*)(src + (size_t)(n0 + r) * FDIM + c4);
        *(float4*)(As + r * LDA + c4) = v;
    }
}

__device__ __forceinline__ void load_B(float* Bs, const float* __restrict__ W) {
    for (int i = threadIdx.x; i < FDIM * FDIM / 4; i += NTH)
        ((float4*)Bs)[i] = ((const float4*)W)[i];
}

// -------- kernel: out = silu(in @ W1 + b1) @ W2 + b2 --------
__global__ void __launch_bounds__(NTH) dense2_kernel(
    const float* __restrict__ in, const float* __restrict__ W1, const float* __restrict__ b1,
    const float* __restrict__ W2, const float* __restrict__ b2,
    float* __restrict__ out, int N) {
    extern __shared__ float sm[];
    float* As = sm;
    float* Bs = sm + TMR * LDA;
    int n0 = blockIdx.x * TMR;
    int trow = threadIdx.x >> 4, tcol = threadIdx.x & 15;

    load_A_rm(As, in, n0, N);
    load_B(Bs, W1);
    __syncthreads();

    ull acc[16][4];
    zero_acc(acc);
    gemm_core(As, Bs, acc, trow, tcol);
    __syncthreads();  // all As/Bs reads done

    float2 bb[4];
#pragma unroll
    for (int jp = 0; jp < 4; ++jp) bb[jp] = *(const float2*)(b1 + tcol * 8 + jp * 2);
#pragma unroll
    for (int i = 0; i < 16; ++i)
#pragma unroll
        for (int jp = 0; jp < 4; ++jp) {
            U64F2 v; v.u = acc[i][jp];
            float x = v.f.x + bb[jp].x;
            float y = v.f.y + bb[jp].y;
            x = x / (1.f + __expf(-x));
            y = y / (1.f + __expf(-y));
            *(float2*)(As + (trow * 16 + i) * LDA + tcol * 8 + jp * 2) = make_float2(x, y);
        }
    load_B(Bs, W2);
    __syncthreads();

    zero_acc(acc);
    gemm_core(As, Bs, acc, trow, tcol);

    float2 b2v[4];
#pragma unroll
    for (int jp = 0; jp < 4; ++jp) b2v[jp] = *(const float2*)(b2 + tcol * 8 + jp * 2);
#pragma unroll
    for (int i = 0; i < 16; ++i) {
        int n = n0 + trow * 16 + i;
        if (n < N) {
#pragma unroll
            for (int jp = 0; jp < 4; ++jp) {
                U64F2 v; v.u = acc[i][jp];
                *(float2*)(out + (size_t)n * FDIM + tcol * 8 + jp * 2) =
                    make_float2(v.f.x + b2v[jp].x, v.f.y + b2v[jp].y);
            }
        }
    }
}

// -------- kernel: M{1,2,3}[c] = mu[:,:,c] @ WT{1,2,3} (planar outputs) --------
__global__ void __launch_bounds__(NTH) muproj_kernel(
    const float* __restrict__ mu,
    const float* __restrict__ WT1, const float* __restrict__ WT2, const float* __restrict__ WT3,
    float* __restrict__ M1, float* __restrict__ M2, float* __restrict__ M3, int N) {
    extern __shared__ float sm[];
    float* As = sm;
    float* Bs = sm + TMR * LDA;
    int n0 = blockIdx.x * TMR;
    int trow = threadIdx.x >> 4, tcol = threadIdx.x & 15;

    const float* Ws[3] = {WT1, WT2, WT3};
    float* Ms[3] = {M1, M2, M3};

    for (int c = 0; c < 3; ++c) {
        __syncthreads();  // prior gemm reads of As done
        // de-interleave plane c of mu tile (strided loads; L2-hot after pass 0)
        for (int i = threadIdx.x; i < TMR * FDIM; i += NTH) {
            int r = i >> 7, f = i & 127;
            float v = 0.f;
            if (n0 + r < N) v = mu[((size_t)(n0 + r) * FDIM + f) * 3 + c];
            As[r * LDA + f] = v;
        }
        for (int w = 0; w < 3; ++w) {
            __syncthreads();  // As visible; prior Bs reads done
            load_B(Bs, Ws[w]);
            __syncthreads();
            ull acc[16][4];
            zero_acc(acc);
            gemm_core(As, Bs, acc, trow, tcol);
            float* dst = Ms[w] + (size_t)c * PLANE;
#pragma unroll
            for (int i = 0; i < 16; ++i) {
                int n = n0 + trow * 16 + i;
                if (n < N) {
#pragma unroll
                    for (int jp = 0; jp < 4; ++jp) {
                        U64F2 v; v.u = acc[i][jp];
                        *(float2*)(dst + (size_t)n * FDIM + tcol * 8 + jp * 2) = v.f;
                    }
                }
            }
        }
    }
}

// -------- kernel: rank-3 tensor contractions -> ms, mv (planar) --------
__global__ void __launch_bounds__(FDIM) combine_kernel(
    const float* __restrict__ T0, const float* __restrict__ T1,
    const float* __restrict__ T2, const float* __restrict__ T3,
    const float* __restrict__ M0, const float* __restrict__ M1,
    const float* __restrict__ M2, const float* __restrict__ M3,
    float* __restrict__ ms, float* __restrict__ mv, int N) {
    int n = blockIdx.x;
    __shared__ float st[40];
    int tid = threadIdx.x;
    if (tid == 0) st[0] = T0[n];
    if (tid < 3) st[1 + tid] = T1[(size_t)n * 3 + tid];
    if (tid >= 32 && tid < 41) st[4 + tid - 32] = T2[(size_t)n * 9 + (tid - 32)];
    if (tid >= 64 && tid < 91) st[13 + tid - 64] = T3[(size_t)n * 27 + (tid - 64)];
    __syncthreads();

    float t0 = st[0];
    float t1[3], t2[9], t3[27];
#pragma unroll
    for (int k = 0; k < 3; ++k) t1[k] = st[1 + k];
#pragma unroll
    for (int k = 0; k < 9; ++k) t2[k] = st[4 + k];
#pragma unroll
    for (int k = 0; k < 27; ++k) t3[k] = st[13 + k];

    size_t base = (size_t)n * FDIM + tid;
    float m0 = M0[base];
    float m1[3], m2[3], m3[3];
#pragma unroll
    for (int c = 0; c < 3; ++c) {
        m1[c] = M1[base + (size_t)c * PLANE];
        m2[c] = M2[base + (size_t)c * PLANE];
        m3[c] = M3[base + (size_t)c * PLANE];
    }

    float s = t0 * m0;
#pragma unroll
    for (int i = 0; i < 3; ++i) s += m1[i] * t1[i];
#pragma unroll
    for (int i = 0; i < 3; ++i)
#pragma unroll
        for (int j = 0; j < 3; ++j) s += m2[i] * m2[j] * t2[i * 3 + j];
#pragma unroll
    for (int i = 0; i < 3; ++i) {
        float mi = m3[i];
#pragma unroll
        for (int j = 0; j < 3; ++j) {
            float mij = mi * m3[j];
#pragma unroll
            for (int k = 0; k < 3; ++k) s += mij * m3[k] * t3[i * 9 + j * 3 + k];
        }
    }
    ms[base] = s;

#pragma unroll
    for (int i = 0; i < 3; ++i) {
        float v = t1[i] * m0;
#pragma unroll
        for (int j = 0; j < 3; ++j) v += t2[i * 3 + j] * m1[j];
#pragma unroll
        for (int j = 0; j < 3; ++j)
#pragma unroll
            for (int k = 0; k < 3; ++k) v += t3[i * 9 + j * 3 + k] * m2[j] * m2[k];
        mv[base + (size_t)i * PLANE] = v;
    }
}

// -------- kernel: mv_out[n,a,c] = sum_f mv[c][n,f] * Wv[f,a] --------
__global__ void __launch_bounds__(NTH) vproj_kernel(
    const float* __restrict__ mv, const float* __restrict__ Wv,
    float* __restrict__ out, int N) {
    extern __shared__ float sm[];
    float* As = sm;
    float* Bs = sm + TMR * LDA;
    int n0 = blockIdx.x * TMR;
    int trow = threadIdx.x >> 4, tcol = threadIdx.x & 15;

    load_B(Bs, Wv);
#pragma unroll 1
    for (int c = 0; c < 3; ++c) {
        __syncthreads();  // prior gemm As reads done
        load_A_rm(As, mv + (size_t)c * PLANE, n0, N);
        __syncthreads();  // As (and, first pass, Bs) visible
        ull acc[16][4];
        zero_acc(acc);
        gemm_core(As, Bs, acc, trow, tcol);
#pragma unroll
        for (int i = 0; i < 16; ++i) {
            int n = n0 + trow * 16 + i;
            if (n < N) {
#pragma unroll
                for (int jp = 0; jp < 4; ++jp) {
                    U64F2 v; v.u = acc[i][jp];
                    int a0 = tcol * 8 + jp * 2;
                    out[(size_t)n * FDIM * 3 + (size_t)a0 * 3 + c] = v.f.x;
                    out[(size_t)n * FDIM * 3 + (size_t)(a0 + 1) * 3 + c] = v.f.y;
                }
            }
        }
    }
}

// -------- launch --------
extern "C" void kernel_launch(void* const* d_in, const int* in_sizes, int n_in,
                              void* d_out, int out_size) {
    const float* feat = (const float*)d_in[0];
    const float* mu   = (const float*)d_in[1];
    const float* T0   = (const float*)d_in[2];
    const float* T1   = (const float*)d_in[3];
    const float* T2   = (const float*)d_in[4];
    const float* T3   = (const float*)d_in[5];
    const float* Wq1  = (const float*)d_in[6];
    const float* bq1  = (const float*)d_in[7];
    const float* Wq2  = (const float*)d_in[8];
    const float* bq2  = (const float*)d_in[9];
    const float* WT1  = (const float*)d_in[10];
    const float* WT2  = (const float*)d_in[11];
    const float* WT3  = (const float*)d_in[12];
    const float* Ws1  = (const float*)d_in[13];
    const float* bs1  = (const float*)d_in[14];
    const float* Ws2  = (const float*)d_in[15];
    const float* bs2  = (const float*)d_in[16];
    const float* Wv   = (const float*)d_in[17];

    int N = in_sizes[0] / FDIM;
    if (N > MAXN) N = MAXN;

    float* out = (float*)d_out;
    float* ms_out = out;                       // [N, 128]
    float* mv_out = out + (size_t)N * FDIM;    // [N, 128, 3]

    size_t smB = (size_t)(TMR * LDA + FDIM * FDIM) * sizeof(float);  // ~163 KB
    cudaFuncSetAttribute(dense2_kernel, cudaFuncAttributeMaxDynamicSharedMemorySize, (int)smB);
    cudaFuncSetAttribute(muproj_kernel, cudaFuncAttributeMaxDynamicSharedMemorySize, (int)smB);
    cudaFuncSetAttribute(vproj_kernel,  cudaFuncAttributeMaxDynamicSharedMemorySize, (int)smB);

    float *pM0, *pM1, *pM2, *pM3, *pms, *pmv;
    cudaGetSymbolAddress((void**)&pM0, g_M0);
    cudaGetSymbolAddress((void**)&pM1, g_M1);
    cudaGetSymbolAddress((void**)&pM2, g_M2);
    cudaGetSymbolAddress((void**)&pM3, g_M3);
    cudaGetSymbolAddress((void**)&pms, g_ms);
    cudaGetSymbolAddress((void**)&pmv, g_mv);

    int nb = (N + TMR - 1) / TMR;

    dense2_kernel<<<nb, NTH, smB>>>(feat, Wq1, bq1, Wq2, bq2, pM0, N);
    muproj_kernel<<<nb, NTH, smB>>>(mu, WT1, WT2, WT3, pM1, pM2, pM3, N);
    combine_kernel<<<N, FDIM>>>(T0, T1, T2, T3, pM0, pM1, pM2, pM3, pms, pmv, N);
    dense2_kernel<<<nb, NTH, smB>>>(pms, Ws1, bs1, Ws2, bs2, ms_out, N);
    vproj_kernel<<<nb, NTH, smB>>>(pmv, Wv, mv_out, N);
}

// round 3
// speedup vs baseline: 1.4322x; 1.4322x over previous
#include <cuda_runtime.h>
#include <math.h>

typedef unsigned long long ull;

#define MAXN  50000
#define FDIM  128
#define TMR   96           // block row tile
#define NTH   256          // threads per block
#define RPT   12           // rows per thread
#define PLANE ((size_t)MAXN * FDIM)

// -------- scratch (allocation-free: __device__ globals) --------
__device__ float g_M0[MAXN * FDIM];
__device__ float g_M1[3][MAXN * FDIM];
__device__ float g_M2[3][MAXN * FDIM];
__device__ float g_M3[3][MAXN * FDIM];
__device__ float g_ms[MAXN * FDIM];
__device__ float g_mv[3][MAXN * FDIM];

// -------- packed fp32 helpers (sm_100+ FFMA2) --------
__device__ __forceinline__ void fma2(ull& d, ull a, ull b) {
    asm("fma.rn.f32x2 %0, %1, %2, %0;" : "+l"(d) : "l"(a), "l"(b));
}
__device__ __forceinline__ ull dup2(float x) {
    ull r; asm("mov.b64 %0, {%1, %1};" : "=l"(r) : "f"(x)); return r;
}
union U64F2 { ull u; float2 f; };

// -------- GEMM core: per-thread 12 rows x 4 cols (2 col-pairs) --------
// As: [TMR][128] row-major, NO padding (A reads are warp-broadcast -> conflict-free).
// Bs: [128][128] row-major. trow = tid>>5 (0..7, = warp id), tcol = lane (0..31).
__device__ __forceinline__ void gemm_core(const float* __restrict__ As,
                                          const float* __restrict__ Bs,
                                          ull acc[RPT][2], int trow, int tcol) {
    const float* a = As + trow * RPT * FDIM;
    const float* b = Bs + tcol * 4;
#pragma unroll 2
    for (int k = 0; k < FDIM; k += 2) {
        ulonglong2 b0 = *(const ulonglong2*)(b + (size_t)k * FDIM);        // B[k][4c..4c+3]
        ulonglong2 b1 = *(const ulonglong2*)(b + (size_t)(k + 1) * FDIM);  // B[k+1][...]
#pragma unroll
        for (int i = 0; i < RPT; ++i) {
            float2 av = *(const float2*)(a + i * FDIM + k);  // broadcast across warp
            ull a0 = dup2(av.x);
            fma2(acc[i][0], a0, b0.x);
            fma2(acc[i][1], a0, b0.y);
            ull a1 = dup2(av.y);
            fma2(acc[i][0], a1, b1.x);
            fma2(acc[i][1], a1, b1.y);
        }
    }
}

__device__ __forceinline__ void zero_acc(ull acc[RPT][2]) {
#pragma unroll
    for (int i = 0; i < RPT; ++i) { acc[i][0] = 0ull; acc[i][1] = 0ull; }
}

__device__ __forceinline__ void load_A_rm(float* As, const float* __restrict__ src,
                                          int n0, int N) {
    for (int i = threadIdx.x; i < TMR * 32; i += NTH) {
        int r = i >> 5;
        int c4 = (i & 31) * 4;
        float4 v = make_float4(0.f, 0.f, 0.f, 0.f);
        if (n0 + r < N) v = *(const float4*)(src + (size_t)(n0 + r) * FDIM + c4);
        *(float4*)(As + r * FDIM + c4) = v;
    }
}

__device__ __forceinline__ void load_B(float* Bs, const float* __restrict__ W) {
    for (int i = threadIdx.x; i < FDIM * FDIM / 4; i += NTH)
        ((float4*)Bs)[i] = ((const float4*)W)[i];
}

// -------- kernel: out = silu(in @ W1 + b1) @ W2 + b2 --------
__global__ void __launch_bounds__(NTH, 2) dense2_kernel(
    const float* __restrict__ in, const float* __restrict__ W1, const float* __restrict__ b1,
    const float* __restrict__ W2, const float* __restrict__ b2,
    float* __restrict__ out, int N) {
    extern __shared__ float sm[];
    float* As = sm;
    float* Bs = sm + TMR * FDIM;
    int n0 = blockIdx.x * TMR;
    int trow = threadIdx.x >> 5, tcol = threadIdx.x & 31;

    load_A_rm(As, in, n0, N);
    load_B(Bs, W1);
    __syncthreads();

    ull acc[RPT][2];
    zero_acc(acc);
    gemm_core(As, Bs, acc, trow, tcol);
    __syncthreads();  // all As/Bs reads done

    float2 bb0 = *(const float2*)(b1 + tcol * 4);
    float2 bb1 = *(const float2*)(b1 + tcol * 4 + 2);
#pragma unroll
    for (int i = 0; i < RPT; ++i) {
        U64F2 v0, v1; v0.u = acc[i][0]; v1.u = acc[i][1];
        float x0 = v0.f.x + bb0.x, x1 = v0.f.y + bb0.y;
        float x2 = v1.f.x + bb1.x, x3 = v1.f.y + bb1.y;
        x0 = x0 / (1.f + __expf(-x0));
        x1 = x1 / (1.f + __expf(-x1));
        x2 = x2 / (1.f + __expf(-x2));
        x3 = x3 / (1.f + __expf(-x3));
        *(float4*)(As + (trow * RPT + i) * FDIM + tcol * 4) = make_float4(x0, x1, x2, x3);
    }
    load_B(Bs, W2);
    __syncthreads();

    zero_acc(acc);
    gemm_core(As, Bs, acc, trow, tcol);

    float2 c0 = *(const float2*)(b2 + tcol * 4);
    float2 c1 = *(const float2*)(b2 + tcol * 4 + 2);
#pragma unroll
    for (int i = 0; i < RPT; ++i) {
        int n = n0 + trow * RPT + i;
        if (n < N) {
            U64F2 v0, v1; v0.u = acc[i][0]; v1.u = acc[i][1];
            *(float4*)(out + (size_t)n * FDIM + tcol * 4) =
                make_float4(v0.f.x + c0.x, v0.f.y + c0.y, v1.f.x + c1.x, v1.f.y + c1.y);
        }
    }
}

// -------- kernel: M{1,2,3}[c] = mu[:,:,c] @ WT{1,2,3} (planar outputs) --------
__global__ void __launch_bounds__(NTH, 2) muproj_kernel(
    const float* __restrict__ mu,
    const float* __restrict__ WT1, const float* __restrict__ WT2, const float* __restrict__ WT3,
    float* __restrict__ M1, float* __restrict__ M2, float* __restrict__ M3, int N) {
    extern __shared__ float sm[];
    float* As = sm;
    float* Bs = sm + TMR * FDIM;
    int n0 = blockIdx.x * TMR;
    int trow = threadIdx.x >> 5, tcol = threadIdx.x & 31;

    const float* Ws[3] = {WT1, WT2, WT3};
    float* Ms[3] = {M1, M2, M3};

    for (int c = 0; c < 3; ++c) {
        __syncthreads();  // prior gemm reads of As done
        // de-interleave plane c of mu tile (L2-hot after first pass)
        for (int i = threadIdx.x; i < TMR * FDIM; i += NTH) {
            int r = i >> 7, f = i & 127;
            float v = 0.f;
            if (n0 + r < N) v = mu[((size_t)(n0 + r) * FDIM + f) * 3 + c];
            As[r * FDIM + f] = v;
        }
        for (int w = 0; w < 3; ++w) {
            __syncthreads();  // As visible; prior Bs reads done
            load_B(Bs, Ws[w]);
            __syncthreads();
            ull acc[RPT][2];
            zero_acc(acc);
            gemm_core(As, Bs, acc, trow, tcol);
            float* dst = Ms[w] + (size_t)c * PLANE;
#pragma unroll
            for (int i = 0; i < RPT; ++i) {
                int n = n0 + trow * RPT + i;
                if (n < N) {
                    U64F2 v0, v1; v0.u = acc[i][0]; v1.u = acc[i][1];
                    *(float4*)(dst + (size_t)n * FDIM + tcol * 4) =
                        make_float4(v0.f.x, v0.f.y, v1.f.x, v1.f.y);
                }
            }
        }
    }
}

// -------- kernel: rank-3 tensor contractions -> ms, mv (planar) --------
__global__ void __launch_bounds__(FDIM) combine_kernel(
    const float* __restrict__ T0, const float* __restrict__ T1,
    const float* __restrict__ T2, const float* __restrict__ T3,
    const float* __restrict__ M0, const float* __restrict__ M1,
    const float* __restrict__ M2, const float* __restrict__ M3,
    float* __restrict__ ms, float* __restrict__ mv, int N) {
    int n = blockIdx.x;
    __shared__ float st[40];
    int tid = threadIdx.x;
    if (tid == 0) st[0] = T0[n];
    if (tid < 3) st[1 + tid] = T1[(size_t)n * 3 + tid];
    if (tid >= 32 && tid < 41) st[4 + tid - 32] = T2[(size_t)n * 9 + (tid - 32)];
    if (tid >= 64 && tid < 91) st[13 + tid - 64] = T3[(size_t)n * 27 + (tid - 64)];
    __syncthreads();

    float t0 = st[0];
    float t1[3], t2[9], t3[27];
#pragma unroll
    for (int k = 0; k < 3; ++k) t1[k] = st[1 + k];
#pragma unroll
    for (int k = 0; k < 9; ++k) t2[k] = st[4 + k];
#pragma unroll
    for (int k = 0; k < 27; ++k) t3[k] = st[13 + k];

    size_t base = (size_t)n * FDIM + tid;
    float m0 = M0[base];
    float m1[3], m2[3], m3[3];
#pragma unroll
    for (int c = 0; c < 3; ++c) {
        m1[c] = M1[base + (size_t)c * PLANE];
        m2[c] = M2[base + (size_t)c * PLANE];
        m3[c] = M3[base + (size_t)c * PLANE];
    }

    float s = t0 * m0;
#pragma unroll
    for (int i = 0; i < 3; ++i) s += m1[i] * t1[i];
#pragma unroll
    for (int i = 0; i < 3; ++i)
#pragma unroll
        for (int j = 0; j < 3; ++j) s += m2[i] * m2[j] * t2[i * 3 + j];
#pragma unroll
    for (int i = 0; i < 3; ++i) {
        float mi = m3[i];
#pragma unroll
        for (int j = 0; j < 3; ++j) {
            float mij = mi * m3[j];
#pragma unroll
            for (int k = 0; k < 3; ++k) s += mij * m3[k] * t3[i * 9 + j * 3 + k];
        }
    }
    ms[base] = s;

#pragma unroll
    for (int i = 0; i < 3; ++i) {
        float v = t1[i] * m0;
#pragma unroll
        for (int j = 0; j < 3; ++j) v += t2[i * 3 + j] * m1[j];
#pragma unroll
        for (int j = 0; j < 3; ++j)
#pragma unroll
            for (int k = 0; k < 3; ++k) v += t3[i * 9 + j * 3 + k] * m2[j] * m2[k];
        mv[base + (size_t)i * PLANE] = v;
    }
}

// -------- kernel: mv_out[n,a,c] = sum_f mv[c][n,f] * Wv[f,a] --------
__global__ void __launch_bounds__(NTH, 2) vproj_kernel(
    const float* __restrict__ mv, const float* __restrict__ Wv,
    float* __restrict__ out, int N) {
    extern __shared__ float sm[];
    float* As = sm;
    float* Bs = sm + TMR * FDIM;
    int n0 = blockIdx.x * TMR;
    int trow = threadIdx.x >> 5, tcol = threadIdx.x & 31;

    load_B(Bs, Wv);
#pragma unroll 1
    for (int c = 0; c < 3; ++c) {
        __syncthreads();  // prior gemm As reads done
        load_A_rm(As, mv + (size_t)c * PLANE, n0, N);
        __syncthreads();  // As (and, first pass, Bs) visible
        ull acc[RPT][2];
        zero_acc(acc);
        gemm_core(As, Bs, acc, trow, tcol);
#pragma unroll
        for (int i = 0; i < RPT; ++i) {
            int n = n0 + trow * RPT + i;
            if (n < N) {
                U64F2 v0, v1; v0.u = acc[i][0]; v1.u = acc[i][1];
                int a0 = tcol * 4;
                float* o = out + (size_t)n * FDIM * 3 + (size_t)a0 * 3 + c;
                o[0] = v0.f.x; o[3] = v0.f.y; o[6] = v1.f.x; o[9] = v1.f.y;
            }
        }
    }
}

// -------- launch --------
extern "C" void kernel_launch(void* const* d_in, const int* in_sizes, int n_in,
                              void* d_out, int out_size) {
    const float* feat = (const float*)d_in[0];
    const float* mu   = (const float*)d_in[1];
    const float* T0   = (const float*)d_in[2];
    const float* T1   = (const float*)d_in[3];
    const float* T2   = (const float*)d_in[4];
    const float* T3   = (const float*)d_in[5];
    const float* Wq1  = (const float*)d_in[6];
    const float* bq1  = (const float*)d_in[7];
    const float* Wq2  = (const float*)d_in[8];
    const float* bq2  = (const float*)d_in[9];
    const float* WT1  = (const float*)d_in[10];
    const float* WT2  = (const float*)d_in[11];
    const float* WT3  = (const float*)d_in[12];
    const float* Ws1  = (const float*)d_in[13];
    const float* bs1  = (const float*)d_in[14];
    const float* Ws2  = (const float*)d_in[15];
    const float* bs2  = (const float*)d_in[16];
    const float* Wv   = (const float*)d_in[17];

    int N = in_sizes[0] / FDIM;
    if (N > MAXN) N = MAXN;

    float* out = (float*)d_out;
    float* ms_out = out;                       // [N, 128]
    float* mv_out = out + (size_t)N * FDIM;    // [N, 128, 3]

    size_t smB = (size_t)(TMR * FDIM + FDIM * FDIM) * sizeof(float);  // 112 KB
    cudaFuncSetAttribute(dense2_kernel, cudaFuncAttributeMaxDynamicSharedMemorySize, (int)smB);
    cudaFuncSetAttribute(muproj_kernel, cudaFuncAttributeMaxDynamicSharedMemorySize, (int)smB);
    cudaFuncSetAttribute(vproj_kernel,  cudaFuncAttributeMaxDynamicSharedMemorySize, (int)smB);

    float *pM0, *pM1, *pM2, *pM3, *pms, *pmv;
    cudaGetSymbolAddress((void**)&pM0, g_M0);
    cudaGetSymbolAddress((void**)&pM1, g_M1);
    cudaGetSymbolAddress((void**)&pM2, g_M2);
    cudaGetSymbolAddress((void**)&pM3, g_M3);
    cudaGetSymbolAddress((void**)&pms, g_ms);
    cudaGetSymbolAddress((void**)&pmv, g_mv);

    int nb = (N + TMR - 1) / TMR;

    dense2_kernel<<<nb, NTH, smB>>>(feat, Wq1, bq1, Wq2, bq2, pM0, N);
    muproj_kernel<<<nb, NTH, smB>>>(mu, WT1, WT2, WT3, pM1, pM2, pM3, N);
    combine_kernel<<<N, FDIM>>>(T0, T1, T2, T3, pM0, pM1, pM2, pM3, pms, pmv, N);
    dense2_kernel<<<nb, NTH, smB>>>(pms, Ws1, bs1, Ws2, bs2, ms_out, N);
    vproj_kernel<<<nb, NTH, smB>>>(pmv, Wv, mv_out, N);
}

// round 6
// speedup vs baseline: 1.5970x; 1.1151x over previous
#include <cuda_runtime.h>
#include <cuda_bf16.h>
#include <cstdint>
#include <math.h>

#define MAXN 50000
#define FDIM 128
#define TILE 128
#define NTH  256
#define PLANE ((size_t)MAXN * FDIM)

// smem: padded bf16 tiles, row stride 136 bf16 = 272 B (ldmatrix conflict-free)
#define LDSB 272u
#define PLB  34816u          // one 128-row plane: 128*272 bytes
#define AHO 0u
#define ALO PLB
#define BHO (2u*PLB)
#define BLO (3u*PLB)
#define SMSZ (4u*PLB)        // 139264 B

// -------- scratch (allocation-free: __device__ globals) --------
__device__ float g_M0[MAXN * FDIM];
__device__ float g_M1[3][MAXN * FDIM];
__device__ float g_M2[3][MAXN * FDIM];
__device__ float g_M3[3][MAXN * FDIM];
__device__ float g_ms[MAXN * FDIM];
__device__ float g_mv[3][MAXN * FDIM];
// pre-split, transposed weight images: [8 weights][ hi 16384 | lo 16384 ] bf16, [out][in] row-major
__device__ __nv_bfloat16 g_Wimg[8][32768];

// ================= helpers =================
__device__ __forceinline__ uint32_t smem_u32(const void* p) {
    uint32_t a;
    asm("{ .reg .u64 t; cvta.to.shared.u64 t, %1; cvt.u32.u64 %0, t; }" : "=r"(a) : "l"(p));
    return a;
}
__device__ __forceinline__ void ldm4(uint32_t* r, uint32_t addr) {
    asm volatile("ldmatrix.sync.aligned.m8n8.x4.shared.b16 {%0,%1,%2,%3}, [%4];"
                 : "=r"(r[0]), "=r"(r[1]), "=r"(r[2]), "=r"(r[3]) : "r"(addr));
}
__device__ __forceinline__ void mma16816(float* c, const uint32_t* a, uint32_t b0, uint32_t b1) {
    asm volatile(
        "mma.sync.aligned.m16n8k16.row.col.f32.bf16.bf16.f32 "
        "{%0,%1,%2,%3}, {%4,%5,%6,%7}, {%8,%9}, {%0,%1,%2,%3};"
        : "+f"(c[0]), "+f"(c[1]), "+f"(c[2]), "+f"(c[3])
        : "r"(a[0]), "r"(a[1]), "r"(a[2]), "r"(a[3]), "r"(b0), "r"(b1));
}
__device__ __forceinline__ void split1(float x, unsigned short& h, unsigned short& l) {
    __nv_bfloat16 hb = __float2bfloat16(x);
    float r = x - __bfloat162float(hb);
    __nv_bfloat16 lb = __float2bfloat16(r);
    h = *(unsigned short*)&hb;
    l = *(unsigned short*)&lb;
}
__device__ __forceinline__ uint32_t pack2(unsigned short a, unsigned short b) {
    return (uint32_t)a | ((uint32_t)b << 16);
}
__device__ __forceinline__ float sigf(float x) { return 1.f / (1.f + __expf(-x)); }

// load fp32 [TILE][128] tile, split hi/lo into padded smem bf16 planes
__device__ __forceinline__ void load_split_A(char* sm, const float* __restrict__ src,
                                             int n0, int N) {
    for (int i = threadIdx.x; i < TILE * 32; i += NTH) {
        int r = i >> 5, c4 = (i & 31) << 2;
        float4 v = make_float4(0.f, 0.f, 0.f, 0.f);
        if (n0 + r < N) v = *(const float4*)(src + (size_t)(n0 + r) * FDIM + c4);
        unsigned short h0, h1, h2, h3, l0, l1, l2, l3;
        split1(v.x, h0, l0); split1(v.y, h1, l1); split1(v.z, h2, l2); split1(v.w, h3, l3);
        uint32_t off = (uint32_t)r * LDSB + (uint32_t)c4 * 2u;
        *(uint2*)(sm + AHO + off) = make_uint2(pack2(h0, h1), pack2(h2, h3));
        *(uint2*)(sm + ALO + off) = make_uint2(pack2(l0, l1), pack2(l2, l3));
    }
}
// copy pre-split weight image (hi+lo, [128][128] bf16 unpadded) into padded smem B planes
__device__ __forceinline__ void copy_B(char* sm, const __nv_bfloat16* __restrict__ img) {
    const uint4* sh = (const uint4*)img;           // 2048 uint4 (hi)
    const uint4* sl = (const uint4*)(img + 16384); // 2048 uint4 (lo)
    for (int i = threadIdx.x; i < 2048; i += NTH) {
        uint32_t row = i >> 4, q = i & 15;
        uint32_t off = row * LDSB + q * 16u;
        *(uint4*)(sm + BHO + off) = sh[i];
        *(uint4*)(sm + BLO + off) = sl[i];
    }
}

// ---- 3-term split GEMM: acc += Ah*Bh^T + Ah*Bl^T + Al*Bh^T over K=128 ----
// warp grid 4(M) x 2(N); warp tile 32x64; acc[mt 2][nidx 8][4]
__device__ __forceinline__ void gemm3(uint32_t sb, int warpM, int warpN, int lane,
                                      float acc[2][8][4]) {
    uint32_t rowA0 = (uint32_t)(warpM * 32 + (lane & 15)) * LDSB;
    uint32_t rowB0 = (uint32_t)(warpN * 64 + (lane & 15)) * LDSB;
    uint32_t kh = (uint32_t)((lane >> 4) * 8) * 2u;
#pragma unroll
    for (int t = 0; t < 3; ++t) {
        uint32_t ab = sb + (t == 2 ? ALO : AHO);
        uint32_t bb = sb + (t == 1 ? BLO : BHO);
#pragma unroll
        for (int kc = 0; kc < 8; ++kc) {
            uint32_t kof = kh + (uint32_t)kc * 32u;  // kc*16 bf16 = 32 B
            uint32_t ar[2][4], br[4][4];
#pragma unroll
            for (int mt = 0; mt < 2; ++mt)
                ldm4(ar[mt], ab + rowA0 + (uint32_t)(mt * 16) * LDSB + kof);
#pragma unroll
            for (int nt = 0; nt < 4; ++nt)
                ldm4(br[nt], bb + rowB0 + (uint32_t)(nt * 16) * LDSB + kof);
#pragma unroll
            for (int mt = 0; mt < 2; ++mt)
#pragma unroll
                for (int nt = 0; nt < 4; ++nt) {
                    mma16816(acc[mt][nt * 2 + 0], ar[mt], br[nt][0], br[nt][2]);
                    mma16816(acc[mt][nt * 2 + 1], ar[mt], br[nt][1], br[nt][3]);
                }
        }
    }
}
__device__ __forceinline__ void zero_acc(float acc[2][8][4]) {
#pragma unroll
    for (int m = 0; m < 2; ++m)
#pragma unroll
        for (int n = 0; n < 8; ++n)
#pragma unroll
            for (int j = 0; j < 4; ++j) acc[m][n][j] = 0.f;
}

// ================= prep: split + transpose all weights =================
struct WPtrs { const float* p[8]; };
__global__ void prep_weights(WPtrs wp) {
    int w = blockIdx.x;
    const float* src = wp.p[w];              // [k][g], g contiguous
    __nv_bfloat16* hi = g_Wimg[w];           // [g][k]
    __nv_bfloat16* lo = g_Wimg[w] + 16384;
    for (int i = threadIdx.x; i < 16384; i += blockDim.x) {
        int k = i >> 7, g = i & 127;
        unsigned short h, l;
        split1(src[i], h, l);
        hi[g * 128 + k] = *(__nv_bfloat16*)&h;
        lo[g * 128 + k] = *(__nv_bfloat16*)&l;
    }
}

// ================= kernels =================
__global__ void __launch_bounds__(NTH) dense2_mma_kernel(
    const float* __restrict__ in,
    const __nv_bfloat16* __restrict__ img1, const float* __restrict__ b1,
    const __nv_bfloat16* __restrict__ img2, const float* __restrict__ b2,
    float* __restrict__ out, int N) {
    extern __shared__ char sm[];
    int tid = threadIdx.x, wid = tid >> 5, lane = tid & 31;
    int warpM = wid >> 1, warpN = wid & 1;
    int n0 = blockIdx.x * TILE;
    uint32_t sb = smem_u32(sm);

    load_split_A(sm, in, n0, N);
    copy_B(sm, img1);
    __syncthreads();

    float acc[2][8][4];
    zero_acc(acc);
    gemm3(sb, warpM, warpN, lane, acc);
    __syncthreads();  // all smem reads done

    // stage 1 epilogue: bias + silu -> split -> A planes
    int r0 = warpM * 32 + (lane >> 2);
    int c0b = warpN * 64 + (lane & 3) * 2;
#pragma unroll
    for (int mt = 0; mt < 2; ++mt)
#pragma unroll
        for (int nidx = 0; nidx < 8; ++nidx) {
            int c = c0b + nidx * 8;
            float2 bb = *(const float2*)(b1 + c);
#pragma unroll
            for (int hrow = 0; hrow < 2; ++hrow) {
                int r = r0 + mt * 16 + hrow * 8;
                float x = acc[mt][nidx][hrow * 2 + 0] + bb.x;
                float y = acc[mt][nidx][hrow * 2 + 1] + bb.y;
                x *= sigf(x); y *= sigf(y);
                unsigned short hx, lx, hy, ly;
                split1(x, hx, lx); split1(y, hy, ly);
                uint32_t off = (uint32_t)r * LDSB + (uint32_t)c * 2u;
                *(uint32_t*)(sm + AHO + off) = pack2(hx, hy);
                *(uint32_t*)(sm + ALO + off) = pack2(lx, ly);
            }
        }
    copy_B(sm, img2);
    __syncthreads();

    zero_acc(acc);
    gemm3(sb, warpM, warpN, lane, acc);

#pragma unroll
    for (int mt = 0; mt < 2; ++mt)
#pragma unroll
        for (int hrow = 0; hrow < 2; ++hrow) {
            int n = n0 + r0 + mt * 16 + hrow * 8;
            if (n < N) {
#pragma unroll
                for (int nidx = 0; nidx < 8; ++nidx) {
                    int c = c0b + nidx * 8;
                    float2 bb = *(const float2*)(b2 + c);
                    *(float2*)(out + (size_t)n * FDIM + c) = make_float2(
                        acc[mt][nidx][hrow * 2 + 0] + bb.x,
                        acc[mt][nidx][hrow * 2 + 1] + bb.y);
                }
            }
        }
}

__global__ void __launch_bounds__(NTH) muproj_mma_kernel(
    const float* __restrict__ mu,
    const __nv_bfloat16* __restrict__ imgT1, const __nv_bfloat16* __restrict__ imgT2,
    const __nv_bfloat16* __restrict__ imgT3,
    float* __restrict__ M1, float* __restrict__ M2, float* __restrict__ M3, int N) {
    extern __shared__ char sm[];
    int tid = threadIdx.x, wid = tid >> 5, lane = tid & 31;
    int warpM = wid >> 1, warpN = wid & 1;
    int n0 = blockIdx.x * TILE;
    uint32_t sb = smem_u32(sm);
    int r0 = warpM * 32 + (lane >> 2);
    int c0b = warpN * 64 + (lane & 3) * 2;

    const __nv_bfloat16* imgs[3] = {imgT1, imgT2, imgT3};
    float* Ms[3] = {M1, M2, M3};

    for (int c = 0; c < 3; ++c) {
        // de-interleave plane c of mu tile -> split into A planes
        for (int i = tid; i < TILE * FDIM; i += NTH) {
            int r = i >> 7, f = i & 127;
            float v = 0.f;
            if (n0 + r < N) v = __ldg(mu + ((size_t)(n0 + r) * FDIM + f) * 3 + c);
            unsigned short h, l;
            split1(v, h, l);
            uint32_t off = (uint32_t)r * LDSB + (uint32_t)f * 2u;
            *(unsigned short*)(sm + AHO + off) = h;
            *(unsigned short*)(sm + ALO + off) = l;
        }
        for (int w = 0; w < 3; ++w) {
            copy_B(sm, imgs[w]);
            __syncthreads();
            float acc[2][8][4];
            zero_acc(acc);
            gemm3(sb, warpM, warpN, lane, acc);
            float* dst = Ms[w] + (size_t)c * PLANE;
#pragma unroll
            for (int mt = 0; mt < 2; ++mt)
#pragma unroll
                for (int hrow = 0; hrow < 2; ++hrow) {
                    int n = n0 + r0 + mt * 16 + hrow * 8;
                    if (n < N) {
#pragma unroll
                        for (int nidx = 0; nidx < 8; ++nidx) {
                            int cc = c0b + nidx * 8;
                            *(float2*)(dst + (size_t)n * FDIM + cc) = make_float2(
                                acc[mt][nidx][hrow * 2 + 0], acc[mt][nidx][hrow * 2 + 1]);
                        }
                    }
                }
            __syncthreads();  // reads of A/B done before overwrite
        }
    }
}

__global__ void __launch_bounds__(NTH) vproj_mma_kernel(
    const float* __restrict__ mv, const __nv_bfloat16* __restrict__ imgV,
    float* __restrict__ out, int N) {
    extern __shared__ char sm[];
    int tid = threadIdx.x, wid = tid >> 5, lane = tid & 31;
    int warpM = wid >> 1, warpN = wid & 1;
    int n0 = blockIdx.x * TILE;
    uint32_t sb = smem_u32(sm);
    int r0 = warpM * 32 + (lane >> 2);
    int c0b = warpN * 64 + (lane & 3) * 2;

    copy_B(sm, imgV);
#pragma unroll 1
    for (int c = 0; c < 3; ++c) {
        load_split_A(sm, mv + (size_t)c * PLANE, n0, N);
        __syncthreads();
        float acc[2][8][4];
        zero_acc(acc);
        gemm3(sb, warpM, warpN, lane, acc);
#pragma unroll
        for (int mt = 0; mt < 2; ++mt)
#pragma unroll
            for (int hrow = 0; hrow < 2; ++hrow) {
                int n = n0 + r0 + mt * 16 + hrow * 8;
                if (n < N) {
                    float* o = out + (size_t)n * FDIM * 3 + c;
#pragma unroll
                    for (int nidx = 0; nidx < 8; ++nidx) {
                        int a = c0b + nidx * 8;
                        o[(size_t)a * 3]       = acc[mt][nidx][hrow * 2 + 0];
                        o[(size_t)(a + 1) * 3] = acc[mt][nidx][hrow * 2 + 1];
                    }
                }
            }
        __syncthreads();  // A reads done before next plane overwrite
    }
}

// ================= combine (rank-3 contractions) =================
__global__ void __launch_bounds__(FDIM) combine_kernel(
    const float* __restrict__ T0, const float* __restrict__ T1,
    const float* __restrict__ T2, const float* __restrict__ T3,
    const float* __restrict__ M0, const float* __restrict__ M1,
    const float* __restrict__ M2, const float* __restrict__ M3,
    float* __restrict__ ms, float* __restrict__ mv, int N) {
    int n = blockIdx.x;
    __shared__ float st[40];
    int tid = threadIdx.x;
    if (tid == 0) st[0] = T0[n];
    if (tid < 3) st[1 + tid] = T1[(size_t)n * 3 + tid];
    if (tid >= 32 && tid < 41) st[4 + tid - 32] = T2[(size_t)n * 9 + (tid - 32)];
    if (tid >= 64 && tid < 91) st[13 + tid - 64] = T3[(size_t)n * 27 + (tid - 64)];
    __syncthreads();

    float t0 = st[0];
    float t1[3], t2[9], t3[27];
#pragma unroll
    for (int k = 0; k < 3; ++k) t1[k] = st[1 + k];
#pragma unroll
    for (int k = 0; k < 9; ++k) t2[k] = st[4 + k];
#pragma unroll
    for (int k = 0; k < 27; ++k) t3[k] = st[13 + k];

    size_t base = (size_t)n * FDIM + tid;
    float m0 = M0[base];
    float m1[3], m2[3], m3[3];
#pragma unroll
    for (int c = 0; c < 3; ++c) {
        m1[c] = M1[base + (size_t)c * PLANE];
        m2[c] = M2[base + (size_t)c * PLANE];
        m3[c] = M3[base + (size_t)c * PLANE];
    }

    float s = t0 * m0;
#pragma unroll
    for (int i = 0; i < 3; ++i) s += m1[i] * t1[i];
#pragma unroll
    for (int i = 0; i < 3; ++i)
#pragma unroll
        for (int j = 0; j < 3; ++j) s += m2[i] * m2[j] * t2[i * 3 + j];
#pragma unroll
    for (int i = 0; i < 3; ++i) {
        float mi = m3[i];
#pragma unroll
        for (int j = 0; j < 3; ++j) {
            float mij = mi * m3[j];
#pragma unroll
            for (int k = 0; k < 3; ++k) s += mij * m3[k] * t3[i * 9 + j * 3 + k];
        }
    }
    ms[base] = s;

#pragma unroll
    for (int i = 0; i < 3; ++i) {
        float v = t1[i] * m0;
#pragma unroll
        for (int j = 0; j < 3; ++j) v += t2[i * 3 + j] * m1[j];
#pragma unroll
        for (int j = 0; j < 3; ++j)
#pragma unroll
            for (int k = 0; k < 3; ++k) v += t3[i * 9 + j * 3 + k] * m2[j] * m2[k];
        mv[base + (size_t)i * PLANE] = v;
    }
}

// ================= launch =================
extern "C" void kernel_launch(void* const* d_in, const int* in_sizes, int n_in,
                              void* d_out, int out_size) {
    const float* feat = (const float*)d_in[0];
    const float* mu   = (const float*)d_in[1];
    const float* T0   = (const float*)d_in[2];
    const float* T1   = (const float*)d_in[3];
    const float* T2   = (const float*)d_in[4];
    const float* T3   = (const float*)d_in[5];
    const float* Wq1  = (const float*)d_in[6];
    const float* bq1  = (const float*)d_in[7];
    const float* Wq2  = (const float*)d_in[8];
    const float* bq2  = (const float*)d_in[9];
    const float* WT1  = (const float*)d_in[10];
    const float* WT2  = (const float*)d_in[11];
    const float* WT3  = (const float*)d_in[12];
    const float* Ws1  = (const float*)d_in[13];
    const float* bs1  = (const float*)d_in[14];
    const float* Ws2  = (const float*)d_in[15];
    const float* bs2  = (const float*)d_in[16];
    const float* Wv   = (const float*)d_in[17];

    int N = in_sizes[0] / FDIM;
    if (N > MAXN) N = MAXN;

    float* out = (float*)d_out;
    float* ms_out = out;
    float* mv_out = out + (size_t)N * FDIM;

    cudaFuncSetAttribute(dense2_mma_kernel, cudaFuncAttributeMaxDynamicSharedMemorySize, SMSZ);
    cudaFuncSetAttribute(muproj_mma_kernel, cudaFuncAttributeMaxDynamicSharedMemorySize, SMSZ);
    cudaFuncSetAttribute(vproj_mma_kernel,  cudaFuncAttributeMaxDynamicSharedMemorySize, SMSZ);

    float *pM0, *pM1, *pM2, *pM3, *pms, *pmv;
    __nv_bfloat16* pW;
    cudaGetSymbolAddress((void**)&pM0, g_M0);
    cudaGetSymbolAddress((void**)&pM1, g_M1);
    cudaGetSymbolAddress((void**)&pM2, g_M2);
    cudaGetSymbolAddress((void**)&pM3, g_M3);
    cudaGetSymbolAddress((void**)&pms, g_ms);
    cudaGetSymbolAddress((void**)&pmv, g_mv);
    cudaGetSymbolAddress((void**)&pW,  g_Wimg);

    WPtrs wp;
    wp.p[0] = Wq1; wp.p[1] = Wq2; wp.p[2] = WT1; wp.p[3] = WT2;
    wp.p[4] = WT3; wp.p[5] = Ws1; wp.p[6] = Ws2; wp.p[7] = Wv;
    prep_weights<<<8, 256>>>(wp);

    int nb = (N + TILE - 1) / TILE;
    dense2_mma_kernel<<<nb, NTH, SMSZ>>>(feat, pW + 0 * 32768, bq1, pW + 1 * 32768, bq2, pM0, N);
    muproj_mma_kernel<<<nb, NTH, SMSZ>>>(mu, pW + 2 * 32768, pW + 3 * 32768, pW + 4 * 32768,
                                         pM1, pM2, pM3, N);
    combine_kernel<<<N, FDIM>>>(T0, T1, T2, T3, pM0, pM1, pM2, pM3, pms, pmv, N);
    dense2_mma_kernel<<<nb, NTH, SMSZ>>>(pms, pW + 5 * 32768, bs1, pW + 6 * 32768, bs2, ms_out, N);
    vproj_mma_kernel<<<nb, NTH, SMSZ>>>(pmv, pW + 7 * 32768, mv_out, N);
}